// round 4
// baseline (speedup 1.0000x reference)
#include <cuda_runtime.h>

#define DIM      4096
#define B        8
#define KV_DIM   1024   // N_KV_HEADS * HEAD_DIM
#define TOTAL    16384

// Scratch (allocation-free rule: __device__ globals)
__device__ __align__(16) float g_x[B * KV_DIM];  // up-proj result  [b][r]
__device__ __align__(16) float g_y[B * DIM];     // down-proj result [b][o]

// ---------------------------------------------------------------------------
// Kernel 1: x[b][r] = sum_k emb[b][k] * Wup[r][k]
// grid = 1024 (one block per output feature r), 128 threads
// Wup row (16 KB) read once; emb (128 KB) stays L2-hot across blocks.
// ---------------------------------------------------------------------------
__global__ void __launch_bounds__(128) up_proj_kernel(
    const float* __restrict__ emb, const float* __restrict__ Wup)
{
    const int r   = blockIdx.x;      // 0..1023
    const int tid = threadIdx.x;
    const float4* w4 = reinterpret_cast<const float4*>(Wup + (size_t)r * DIM);

    float acc[B];
#pragma unroll
    for (int b = 0; b < B; b++) acc[b] = 0.f;

#pragma unroll
    for (int k = 0; k < 8; k++) {                 // 1024 float4 / 128 threads
        const int q = tid + k * 128;
        const float4 w = __ldg(&w4[q]);
#pragma unroll
        for (int b = 0; b < B; b++) {
            const float4 e = __ldg(reinterpret_cast<const float4*>(emb + (size_t)b * DIM) + q);
            acc[b] += w.x * e.x + w.y * e.y + w.z * e.z + w.w * e.w;
        }
    }

    // reduce: warp shuffle, then 4 warp-partials per b in smem
    __shared__ float s_part[B * 4];
#pragma unroll
    for (int b = 0; b < B; b++) {
        float v = acc[b];
#pragma unroll
        for (int off = 16; off; off >>= 1) v += __shfl_down_sync(0xffffffffu, v, off);
        if ((tid & 31) == 0) s_part[b * 4 + (tid >> 5)] = v;
    }
    __syncthreads();
    if (tid < B) {
        const float v = s_part[tid * 4 + 0] + s_part[tid * 4 + 1]
                      + s_part[tid * 4 + 2] + s_part[tid * 4 + 3];
        g_x[tid * KV_DIM + r] = v;
    }
}

// ---------------------------------------------------------------------------
// Kernel 2: y[b][o] = sum_j val[b][j] * Wdown[o][j]
//   val[b][j] = x[b][ ((j>>9)<<7) | (j&127) ]   (repeat-interleave remap)
// grid = 4096 (one block per output feature o), 128 threads
// Within any aligned group of 4 consecutive j, the remap is contiguous,
// so val can still be loaded as float4. Wdown (64 MB) read exactly once.
// ---------------------------------------------------------------------------
__global__ void __launch_bounds__(128) down_proj_kernel(
    const float* __restrict__ Wdown)
{
    const int o   = blockIdx.x;      // 0..4095
    const int tid = threadIdx.x;
    const float4* w4 = reinterpret_cast<const float4*>(Wdown + (size_t)o * DIM);

    float acc[B];
#pragma unroll
    for (int b = 0; b < B; b++) acc[b] = 0.f;

#pragma unroll
    for (int k = 0; k < 8; k++) {
        const int q  = tid + k * 128;
        const float4 w = __ldg(&w4[q]);
        const int j0 = 4 * q;
        const int m0 = ((j0 >> 9) << 7) | (j0 & 127);   // remapped, float4-aligned
#pragma unroll
        for (int b = 0; b < B; b++) {
            const float4 v = *reinterpret_cast<const float4*>(&g_x[b * KV_DIM + m0]);
            acc[b] += w.x * v.x + w.y * v.y + w.z * v.z + w.w * v.w;
        }
    }

    __shared__ float s_part[B * 4];
#pragma unroll
    for (int b = 0; b < B; b++) {
        float v = acc[b];
#pragma unroll
        for (int off = 16; off; off >>= 1) v += __shfl_down_sync(0xffffffffu, v, off);
        if ((tid & 31) == 0) s_part[b * 4 + (tid >> 5)] = v;
    }
    __syncthreads();
    if (tid < B) {
        const float v = s_part[tid * 4 + 0] + s_part[tid * 4 + 1]
                      + s_part[tid * 4 + 2] + s_part[tid * 4 + 3];
        g_y[tid * DIM + o] = v;
    }
}

// ---------------------------------------------------------------------------
// Kernel 3: out[t][:] = y[batch(t)][:]   — the 256 MB broadcast (HBM-bound)
// grid = 4096 blocks x 128 threads, 4 tokens per block, 8 float4/thread/token.
// seqlen dtype (int32 vs int64) auto-detected on device.
// Streaming stores (__stcs) keep y resident in L2.
// ---------------------------------------------------------------------------
__global__ void __launch_bounds__(128) broadcast_kernel(
    const int* __restrict__ seqlen_raw, float* __restrict__ out)
{
    __shared__ int s_off[B + 1];
    if (threadIdx.x == 0) {
        int sum32 = 0;
#pragma unroll
        for (int i = 0; i < B; i++) sum32 += seqlen_raw[i];
        const bool is64 = (sum32 != TOTAL);   // int64: low word at index 2*i (LE)
        int acc = 0;
#pragma unroll
        for (int i = 0; i < B; i++) {
            s_off[i] = acc;
            acc += is64 ? seqlen_raw[2 * i] : seqlen_raw[i];
        }
        s_off[B] = acc;
    }
    __syncthreads();

    const int tid = threadIdx.x;
#pragma unroll
    for (int t = 0; t < 4; t++) {
        const int token = blockIdx.x * 4 + t;
        // linear scan over 8 prefix offsets
        int b = 0;
#pragma unroll
        for (int i = 1; i < B; i++) b += (token >= s_off[i]);

        const float4* y4 = reinterpret_cast<const float4*>(&g_y[b * DIM]);
        float4* o4 = reinterpret_cast<float4*>(out + (size_t)token * DIM);
#pragma unroll
        for (int k = 0; k < 8; k++) {
            const int q = tid + k * 128;
            __stcs(&o4[q], __ldg(&y4[q]));
        }
    }
}

// ---------------------------------------------------------------------------
// Inputs (metadata order): embedding [8,4096] f32, W_up [1024,4096] f32,
// W_down [4096,4096] f32, seqlen [8] int. Output: [16384,4096] f32.
// ---------------------------------------------------------------------------
extern "C" void kernel_launch(void* const* d_in, const int* in_sizes, int n_in,
                              void* d_out, int out_size)
{
    const float* emb    = (const float*)d_in[0];
    const float* Wup    = (const float*)d_in[1];
    const float* Wdown  = (const float*)d_in[2];
    const int*   seqlen = (const int*)d_in[3];
    float* out = (float*)d_out;

    up_proj_kernel<<<KV_DIM, 128>>>(emb, Wup);
    down_proj_kernel<<<DIM, 128>>>(Wdown);
    broadcast_kernel<<<TOTAL / 4, 128>>>(seqlen, out);
}